// round 16
// baseline (speedup 1.0000x reference)
#include <cuda_runtime.h>
#include <cuda_fp16.h>
#include <cstdint>

// ============================================================================
// Problem constants
// ============================================================================
#define N_NODES 10000
#define N_EDGES 160000
#define D_IN    512
#define D_HID   1024
#define NMB     79          // ceil(N_NODES/128) M-blocks

// Persistent tile queue (phase E), interleaved:
//   t in [0, 948):  group m = t/12; slot<4 -> agg sub-tile, else GEMM1 tile
//   t in [948, 1580): GEMM2 half-K chunks
#define G1_SECTION 948      // 79 * 12
#define TILE_TOTAL 1580     // + 79 * 8

// ============================================================================
// Scratch (static __device__ arrays — no allocation allowed)
// ============================================================================
__device__ __half g_Ah[(size_t)N_NODES * D_IN];    // rst hi   [N, 512]
__device__ __half g_Al[(size_t)N_NODES * D_IN];    // rst lo
__device__ __half g_Hh[(size_t)N_NODES * D_HID];   // hidden hi [N, 1024]
__device__ __half g_Hl[(size_t)N_NODES * D_HID];   // hidden lo
__device__ __half g_W1h[(size_t)D_HID * D_IN];     // W1^T hi [1024, 512]
__device__ __half g_W1l[(size_t)D_HID * D_IN];
__device__ __half g_W2h[(size_t)D_IN * D_HID];     // W2^T hi [512, 1024]
__device__ __half g_W2l[(size_t)D_IN * D_HID];
__device__ int      g_cnt[N_NODES];
__device__ int      g_off[N_NODES];
__device__ int      g_cur[N_NODES];
__device__ int      g_csr[N_EDGES];
__device__ int      g_base_ctr;
__device__ int      g_qhead;
__device__ int      g_adone[NMB];
__device__ int      g_hdone[NMB];
__device__ unsigned g_barcnt[4];    // zero-init; self-resetting
__device__ unsigned g_bargen[4];    // monotonic generation (replay-safe)

// ============================================================================
// Helpers
// ============================================================================
__device__ __forceinline__ uint32_t smem_to_u32(const void* p) {
    uint32_t a;
    asm("{ .reg .u64 t; cvta.to.shared.u64 t, %1; cvt.u32.u64 %0, t; }" : "=r"(a) : "l"(p));
    return a;
}

__device__ __forceinline__ void split_h(float x, __half& h, __half& l) {
    h = __float2half_rn(x);
    l = __float2half_rn(x - __half2float(h));
}

__device__ __forceinline__ void wait_flag(volatile int* f, int target) {
    while (*f < target) __nanosleep(64);
    __threadfence();   // acquire
}

__device__ __forceinline__ void ldsm_x4(uint32_t& r0, uint32_t& r1, uint32_t& r2, uint32_t& r3,
                                        uint32_t addr) {
    asm volatile("ldmatrix.sync.aligned.m8n8.x4.shared.b16 {%0,%1,%2,%3}, [%4];"
                 : "=r"(r0), "=r"(r1), "=r"(r2), "=r"(r3) : "r"(addr));
}

// Sense-reversing software grid barrier. Safe: all CTAs resident (occ=2 forced).
__device__ __forceinline__ void gbar(int id) {
    __syncthreads();
    if (threadIdx.x == 0) {
        volatile unsigned* genp = &g_bargen[id];
        unsigned gen = *genp;
        __threadfence();                         // release my writes
        unsigned old = atomicAdd(&g_barcnt[id], 1u);
        if (old == gridDim.x - 1u) {
            g_barcnt[id] = 0u;
            __threadfence();
            atomicAdd(&g_bargen[id], 1u);        // release all
        } else {
            while (*genp == gen) __nanosleep(32);
        }
        __threadfence();                         // acquire
    }
    __syncthreads();
}

// ============================================================================
// Phase bodies
// ============================================================================
__device__ __forceinline__ void transpose_split_tile256(const float* __restrict__ in,
                                                        __half* __restrict__ outh,
                                                        __half* __restrict__ outl,
                                                        int R, int C, int bx, int by,
                                                        float* tbuf /* 32*33 */) {
    int tx = threadIdx.x & 31, ty = threadIdx.x >> 5;   // 32 x 8
    #pragma unroll
    for (int j = 0; j < 32; j += 8)
        tbuf[(ty + j) * 33 + tx] = in[(size_t)(by + ty + j) * C + bx + tx];
    __syncthreads();
    #pragma unroll
    for (int j = 0; j < 32; j += 8) {
        float x = tbuf[tx * 33 + ty + j];
        __half h, l; split_h(x, h, l);
        size_t o = (size_t)(bx + ty + j) * R + by + tx;
        outh[o] = h; outl[o] = l;
    }
    __syncthreads();
}

__device__ __forceinline__ void f4add(float4& a, const float4 b) {
    a.x += b.x; a.y += b.y; a.z += b.z; a.w += b.w;
}

__device__ __forceinline__ void store_split4(__half* ph, __half* pl, size_t off, float4 v) {
    __half hx, hy, hz, hw, lx, ly, lz, lw;
    split_h(v.x, hx, lx); split_h(v.y, hy, ly);
    split_h(v.z, hz, lz); split_h(v.w, hw, lw);
    *(__half2*)(ph + off)     = __halves2half2(hx, hy);
    *(__half2*)(ph + off + 2) = __halves2half2(hz, hw);
    *(__half2*)(pl + off)     = __halves2half2(lx, ly);
    *(__half2*)(pl + off + 2) = __halves2half2(lz, lw);
}

// One node per warp: gather-sum + GIN combine -> split fp16; pre-init out=feat+b2.
__device__ __forceinline__ void agg_node(int node, int lane,
                                         const float* __restrict__ feat, float ep,
                                         const float* __restrict__ b2,
                                         float* __restrict__ out) {
    float4 a0 = make_float4(0.f, 0.f, 0.f, 0.f), a1 = a0, a2 = a0, a3 = a0;
    int e = g_off[node], e1 = e + g_cnt[node];
    const float4* F = (const float4*)feat;

    for (; e + 1 < e1; e += 2) {
        const float4* p0 = F + (size_t)g_csr[e]     * (D_IN / 4);
        const float4* p1 = F + (size_t)g_csr[e + 1] * (D_IN / 4);
        float4 v00 = p0[lane], v01 = p0[lane + 32], v02 = p0[lane + 64], v03 = p0[lane + 96];
        float4 v10 = p1[lane], v11 = p1[lane + 32], v12 = p1[lane + 64], v13 = p1[lane + 96];
        f4add(a0, v00); f4add(a1, v01); f4add(a2, v02); f4add(a3, v03);
        f4add(a0, v10); f4add(a1, v11); f4add(a2, v12); f4add(a3, v13);
    }
    if (e < e1) {
        const float4* p0 = F + (size_t)g_csr[e] * (D_IN / 4);
        f4add(a0, p0[lane]); f4add(a1, p0[lane + 32]);
        f4add(a2, p0[lane + 64]); f4add(a3, p0[lane + 96]);
    }

    const float4* fn = F + (size_t)node * (D_IN / 4);
    const float4* B2 = (const float4*)b2;
    float4* O = (float4*)out + (size_t)node * (D_IN / 4);
    size_t base = (size_t)node * D_IN;
    #pragma unroll
    for (int q = 0; q < 4; q++) {
        float4 f = fn[lane + 32 * q];
        float4 a = (q == 0) ? a0 : (q == 1) ? a1 : (q == 2) ? a2 : a3;
        float4 r = make_float4(fmaf(ep, f.x, a.x), fmaf(ep, f.y, a.y),
                               fmaf(ep, f.z, a.z), fmaf(ep, f.w, a.w));
        store_split4(g_Ah, g_Al, base + (lane + 32 * q) * 4, r);
        float4 bb = B2[lane + 32 * q];
        O[lane + 32 * q] = make_float4(f.x + bb.x, f.y + bb.y, f.z + bb.z, f.w + bb.w);
    }
}

// ============================================================================
// 3xFP16 GEMM tile body (R14-proven): 128x128 out, K=512, 2-stage cp.async,
// 80B-padded rows, ldmatrix frags, term-major MMA order, non-volatile mma.
// acc += Ah*Bh + Ah*Bl + Al*Bh  (f32 accum; lo*lo dropped).
// ============================================================================
#define BM 128
#define BN 128
#define BK 32
#define KLOOP 512
#define HROW 40
#define HROWB 80
#define HTILE_H (BM * HROW)
#define HTILE_B (HTILE_H * 2)
#define STAGE_B (4 * HTILE_B)
#define GEMM_SMEM (2 * STAGE_B)       // 81920

__device__ __forceinline__ void cp_async16(uint32_t dst, const void* src, int src_sz) {
    asm volatile("cp.async.cg.shared.global [%0], [%1], 16, %2;"
                 :: "r"(dst), "l"(src), "r"(src_sz));
}

__device__ __forceinline__ void load_tile_p(uint32_t sbase,
                                            const __half* __restrict__ Ah, const __half* __restrict__ Al,
                                            const __half* __restrict__ Bh, const __half* __restrict__ Bl,
                                            int lda, int ldb, int m0, int n0, int k0, int tid) {
    #pragma unroll
    for (int i = 0; i < 2; i++) {
        int idx = tid + i * 256;
        int row = idx >> 2, c8 = idx & 3;
        uint32_t doff = (uint32_t)(row * HROWB + c8 * 16);
        int gm = m0 + row;
        int ok = gm < N_NODES;
        size_t aoff = (size_t)(ok ? gm : 0) * lda + k0 + c8 * 8;
        size_t boff = (size_t)(n0 + row) * ldb + k0 + c8 * 8;
        cp_async16(sbase + doff,                Ah + aoff, ok ? 16 : 0);
        cp_async16(sbase + HTILE_B + doff,      Al + aoff, ok ? 16 : 0);
        cp_async16(sbase + 2 * HTILE_B + doff,  Bh + boff, 16);
        cp_async16(sbase + 3 * HTILE_B + doff,  Bl + boff, 16);
    }
}

// NOTE: NOT volatile — pure register dataflow, lets ptxas schedule/interleave.
__device__ __forceinline__ void mma_f16(float d[4], const uint32_t a[4], const uint32_t b[2]) {
    asm("mma.sync.aligned.m16n8k16.row.col.f32.f16.f16.f32 "
        "{%0,%1,%2,%3}, {%4,%5,%6,%7}, {%8,%9}, {%0,%1,%2,%3};"
        : "+f"(d[0]), "+f"(d[1]), "+f"(d[2]), "+f"(d[3])
        : "r"(a[0]), "r"(a[1]), "r"(a[2]), "r"(a[3]), "r"(b[0]), "r"(b[1]));
}

__device__ __forceinline__ void gemm_tile_body(
    uint32_t sb, int tid,
    const __half* __restrict__ Ah, const __half* __restrict__ Al, int lda,
    const __half* __restrict__ Bh, const __half* __restrict__ Bl, int ldb,
    int m0, int n0,
    const float* __restrict__ bias,
    float* __restrict__ outp,
    __half* __restrict__ outH, __half* __restrict__ outL, int outld)
{
    const int wid = tid >> 5, lane = tid & 31;
    const int wm = wid & 1, wn = wid >> 1;       // warp tile: 64 (m) x 32 (n)
    const int lg = lane >> 2, lt = lane & 3;

    // ldmatrix per-lane address offsets
    const uint32_t aLane = (uint32_t)((lane & 15) * HROWB + (lane >> 4) * 16);
    const uint32_t bLane = (uint32_t)((((lane & 7) + ((lane >> 4) << 3)) * HROWB)
                                      + ((lane >> 3) & 1) * 16);

    float acc[4][4][4];
    #pragma unroll
    for (int i = 0; i < 4; i++)
        #pragma unroll
        for (int j = 0; j < 4; j++)
            #pragma unroll
            for (int c = 0; c < 4; c++) acc[i][j][c] = 0.f;

    const int nk = KLOOP / BK;  // 16
    load_tile_p(sb, Ah, Al, Bh, Bl, lda, ldb, m0, n0, 0, tid);
    asm volatile("cp.async.commit_group;" ::: "memory");
    load_tile_p(sb + STAGE_B, Ah, Al, Bh, Bl, lda, ldb, m0, n0, BK, tid);
    asm volatile("cp.async.commit_group;" ::: "memory");

    for (int kc = 0; kc < nk; kc++) {
        asm volatile("cp.async.wait_group 1;" ::: "memory");
        __syncthreads();
        const int buf = kc & 1;
        const uint32_t tAh = sb + buf * STAGE_B;
        const uint32_t tAl = tAh + HTILE_B;
        const uint32_t tBh = tAl + HTILE_B;
        const uint32_t tBl = tBh + HTILE_B;
        const uint32_t aBaseH = tAh + (uint32_t)(wm * 64) * HROWB + aLane;
        const uint32_t aBaseL = tAl + (uint32_t)(wm * 64) * HROWB + aLane;
        const uint32_t bBaseH = tBh + (uint32_t)(wn * 32) * HROWB + bLane;
        const uint32_t bBaseL = tBl + (uint32_t)(wn * 32) * HROWB + bLane;

        #pragma unroll
        for (int kk = 0; kk < BK; kk += 16) {
            uint32_t bh[4][2], bl[4][2];
            #pragma unroll
            for (int njp = 0; njp < 2; njp++) {
                uint32_t o = (uint32_t)(njp * 16 * HROWB + kk * 2);
                ldsm_x4(bh[2 * njp][0], bh[2 * njp][1], bh[2 * njp + 1][0], bh[2 * njp + 1][1],
                        bBaseH + o);
                ldsm_x4(bl[2 * njp][0], bl[2 * njp][1], bl[2 * njp + 1][0], bl[2 * njp + 1][1],
                        bBaseL + o);
            }
            #pragma unroll
            for (int mi = 0; mi < 4; mi++) {
                uint32_t o = (uint32_t)(mi * 16 * HROWB + kk * 2);
                uint32_t ah[4], al[4];
                ldsm_x4(ah[0], ah[1], ah[2], ah[3], aBaseH + o);
                ldsm_x4(al[0], al[1], al[2], al[3], aBaseL + o);
                // Term-major order: dependency distance on each acc = 4 MMAs.
                #pragma unroll
                for (int nj = 0; nj < 4; nj++) mma_f16(acc[mi][nj], ah, bl[nj]); // hi*lo
                #pragma unroll
                for (int nj = 0; nj < 4; nj++) mma_f16(acc[mi][nj], al, bh[nj]); // lo*hi
                #pragma unroll
                for (int nj = 0; nj < 4; nj++) mma_f16(acc[mi][nj], ah, bh[nj]); // hi*hi
            }
        }
        __syncthreads();
        if (kc + 2 < nk)
            load_tile_p(sb + (kc & 1) * STAGE_B, Ah, Al, Bh, Bl, lda, ldb,
                        m0, n0, (kc + 2) * BK, tid);
        asm volatile("cp.async.commit_group;" ::: "memory");
    }
    asm volatile("cp.async.wait_group 0;" ::: "memory");

    #pragma unroll
    for (int mi = 0; mi < 4; mi++) {
        #pragma unroll
        for (int half = 0; half < 2; half++) {
            int gm = m0 + wm * 64 + mi * 16 + lg + half * 8;
            if (gm >= N_NODES) continue;
            #pragma unroll
            for (int nj = 0; nj < 4; nj++) {
                int gn = n0 + wn * 32 + nj * 8 + 2 * lt;
                float vx = acc[mi][nj][half * 2 + 0];
                float vy = acc[mi][nj][half * 2 + 1];
                if (outH) {
                    float2 bv = *(const float2*)(bias + gn);
                    vx = fmaxf(vx + bv.x, 0.f);
                    vy = fmaxf(vy + bv.y, 0.f);
                    __half hx, hy, lx, ly;
                    split_h(vx, hx, lx); split_h(vy, hy, ly);
                    *(__half2*)(outH + (size_t)gm * outld + gn) = __halves2half2(hx, hy);
                    *(__half2*)(outL + (size_t)gm * outld + gn) = __halves2half2(lx, ly);
                } else {
                    atomicAdd(outp + (size_t)gm * D_IN + gn,     vx);
                    atomicAdd(outp + (size_t)gm * D_IN + gn + 1, vy);
                }
            }
        }
    }
}

// ============================================================================
// THE single persistent kernel: CSR build + transposes + agg + GEMM1 + GEMM2
// ============================================================================
__global__ __launch_bounds__(256, 2) void mono_kernel(
    const float* __restrict__ feat,
    const float* __restrict__ W1, const float* __restrict__ b1,
    const float* __restrict__ W2, const float* __restrict__ b2,
    const float* __restrict__ eps,
    const int* __restrict__ src, const int* __restrict__ dst,
    float* __restrict__ out)
{
    extern __shared__ char smem[];
    __shared__ int s_t;
    __shared__ int s_ws[8];
    __shared__ int s_blkbase;
    uint32_t sb = smem_to_u32(smem);
    const int tid = threadIdx.x, wid = tid >> 5, lane = tid & 31;
    const int cta = blockIdx.x, nctas = gridDim.x;

    // ---- Phase A: zero counts + flags + queue
    for (int i = cta * 256 + tid; i < N_NODES; i += nctas * 256) g_cnt[i] = 0;
    if (cta == 0) {
        if (tid < NMB) { g_adone[tid] = 0; g_hdone[tid] = 0; }
        if (tid == 200) { g_base_ctr = 0; g_qhead = 0; }
    }
    gbar(0);

    // ---- Phase B: edge histogram + weight transposes (independent, overlap)
    {
        int echunk = (N_EDGES + nctas - 1) / nctas;
        int e0 = cta * echunk, e1 = min(e0 + echunk, N_EDGES);
        for (int i = e0 + tid; i < e1; i += 256) atomicAdd(&g_cnt[dst[i]], 1);

        int tchunk = (1024 + nctas - 1) / nctas;   // 1024 transpose tiles
        int t0 = cta * tchunk, t1 = min(t0 + tchunk, 1024);
        for (int tt = t0; tt < t1; tt++) {
            __syncthreads();
            if (tt < 512) {
                int bx = (tt & 31) * 32, by = (tt >> 5) * 32;  // W1 [512,1024]
                transpose_split_tile256(W1, g_W1h, g_W1l, D_IN, D_HID, bx, by, (float*)smem);
            } else {
                int idx = tt - 512;
                int bx = (idx & 15) * 32, by = (idx >> 4) * 32; // W2 [1024,512]
                transpose_split_tile256(W2, g_W2h, g_W2l, D_HID, D_IN, bx, by, (float*)smem);
            }
        }
    }
    gbar(1);

    // ---- Phase C: block scan + atomic base (first 40 CTAs)
    if (cta < (N_NODES + 255) / 256) {
        int i = cta * 256 + tid;
        int v = (i < N_NODES) ? g_cnt[i] : 0;
        int x = v;
        #pragma unroll
        for (int o = 1; o < 32; o <<= 1) {
            int y = __shfl_up_sync(0xFFFFFFFFu, x, o);
            if ((tid & 31) >= o) x += y;
        }
        if ((tid & 31) == 31) s_ws[wid] = x;
        __syncthreads();
        if (tid == 0) {
            int s = 0;
            #pragma unroll
            for (int j = 0; j < 8; j++) { int tmp = s_ws[j]; s_ws[j] = s; s += tmp; }
            s_blkbase = atomicAdd(&g_base_ctr, s);
        }
        __syncthreads();
        int ex = s_blkbase + s_ws[wid] + x - v;
        if (i < N_NODES) { g_off[i] = ex; g_cur[i] = ex; }
    }
    gbar(2);

    // ---- Phase D: CSR scatter
    {
        int echunk = (N_EDGES + nctas - 1) / nctas;
        int e0 = cta * echunk, e1 = min(e0 + echunk, N_EDGES);
        for (int i = e0 + tid; i < e1; i += 256) {
            int d = dst[i];
            int p = atomicAdd(&g_cur[d], 1);
            g_csr[p] = src[i];
        }
    }
    gbar(3);

    // ---- Phase E: tile queue, agg+GEMM1 interleaved per m-group, then GEMM2
    const float ep = 1.0f + eps[0];
    for (;;) {
        __syncthreads();
        if (tid == 0) s_t = atomicAdd(&g_qhead, 1);
        __syncthreads();
        int t = s_t;
        if (t >= TILE_TOTAL) return;

        if (t < G1_SECTION) {
            int m = t / 12, slot = t - m * 12;
            if (slot < 4) {
                // ---- aggregate sub-tile: nodes [(m*4+slot)*32, +32)
                int base = (m * 4 + slot) * 32;
                #pragma unroll
                for (int i = 0; i < 4; i++) {
                    int node = base + wid * 4 + i;
                    if (node < N_NODES) agg_node(node, lane, feat, ep, b2, out);
                }
                __threadfence();
                __syncthreads();
                if (tid == 0) atomicAdd(&g_adone[m], 1);
            } else {
                // ---- GEMM1 tile (m, n = slot-4)
                int n = slot - 4;
                wait_flag(&g_adone[m], 4);
                gemm_tile_body(sb, tid,
                               g_Ah, g_Al, D_IN, g_W1h, g_W1l, D_IN,
                               m * 128, n * 128, b1, nullptr, g_Hh, g_Hl, D_HID);
                __threadfence();
                __syncthreads();
                if (tid == 0) atomicAdd(&g_hdone[m], 1);
            }
        } else {
            // ---- GEMM2 half-K chunk
            int u = t - G1_SECTION;
            int m = u >> 3, r = u & 7, n2 = r >> 1, kc = r & 1;
            wait_flag(&g_hdone[m], 8);
            gemm_tile_body(sb, tid,
                           g_Hh + kc * 512, g_Hl + kc * 512, D_HID,
                           g_W2h + kc * 512, g_W2l + kc * 512, D_HID,
                           m * 128, n2 * 128, nullptr, out, nullptr, nullptr, 0);
        }
    }
}

// ============================================================================
// kernel_launch — ONE launch
// ============================================================================
extern "C" void kernel_launch(void* const* d_in, const int* in_sizes, int n_in,
                              void* d_out, int out_size) {
    const float* feat = (const float*)d_in[0];
    const float* W1   = (const float*)d_in[1];
    const float* b1   = (const float*)d_in[2];
    const float* W2   = (const float*)d_in[3];
    const float* b2   = (const float*)d_in[4];
    const float* eps  = (const float*)d_in[5];
    const int*   src  = (const int*)d_in[6];
    const int*   dst  = (const int*)d_in[7];
    float* out = (float*)d_out;

    static int grid = 0;
    if (grid == 0) {
        int nsm = 148;
        cudaDeviceGetAttribute(&nsm, cudaDevAttrMultiProcessorCount, 0);
        grid = 2 * nsm;   // matches __launch_bounds__(256, 2): all CTAs resident
    }

    cudaFuncSetAttribute(mono_kernel,
                         cudaFuncAttributeMaxDynamicSharedMemorySize, GEMM_SMEM);

    mono_kernel<<<grid, 256, GEMM_SMEM>>>(feat, W1, b1, W2, b2, eps, src, dst, out);
}

// round 17
// speedup vs baseline: 1.2203x; 1.2203x over previous
#include <cuda_runtime.h>
#include <cuda_fp16.h>
#include <cstdint>

// ============================================================================
// Problem constants
// ============================================================================
#define N_NODES 10000
#define N_EDGES 160000
#define D_IN    512
#define D_HID   1024
#define NMB     79          // ceil(N_NODES/128) M-blocks

// Persistent tile queue layout (phase E) — R14 ordering
#define TILE_AGG_END 316    // 79 * 4 agg sub-tiles (32 nodes each)
#define TILE_G1_END  948    // + 79 * 8 GEMM1 tiles
#define TILE_TOTAL   1580   // + 79 * 8 GEMM2 half-K chunks

// ============================================================================
// Scratch (static __device__ arrays — no allocation allowed)
// ============================================================================
__device__ __half g_Ah[(size_t)N_NODES * D_IN];    // rst hi   [N, 512]
__device__ __half g_Al[(size_t)N_NODES * D_IN];    // rst lo
__device__ __half g_Hh[(size_t)N_NODES * D_HID];   // hidden hi [N, 1024]
__device__ __half g_Hl[(size_t)N_NODES * D_HID];   // hidden lo
__device__ __half g_W1h[(size_t)D_HID * D_IN];     // W1^T hi [1024, 512]
__device__ __half g_W1l[(size_t)D_HID * D_IN];
__device__ __half g_W2h[(size_t)D_IN * D_HID];     // W2^T hi [512, 1024]
__device__ __half g_W2l[(size_t)D_IN * D_HID];
__device__ int      g_cnt[N_NODES];
__device__ int      g_off[N_NODES];
__device__ int      g_cur[N_NODES];
__device__ int      g_csr[N_EDGES];
__device__ int      g_base_ctr;
__device__ int      g_qhead;
__device__ int      g_adone[NMB];
__device__ int      g_hdone[NMB];
__device__ unsigned g_barcnt[4];    // zero-init; self-resetting
__device__ unsigned g_bargen[4];    // monotonic generation (replay-safe)

// ============================================================================
// Helpers
// ============================================================================
__device__ __forceinline__ uint32_t smem_to_u32(const void* p) {
    uint32_t a;
    asm("{ .reg .u64 t; cvta.to.shared.u64 t, %1; cvt.u32.u64 %0, t; }" : "=r"(a) : "l"(p));
    return a;
}

__device__ __forceinline__ void split_h(float x, __half& h, __half& l) {
    h = __float2half_rn(x);
    l = __float2half_rn(x - __half2float(h));
}

__device__ __forceinline__ void wait_flag(volatile int* f, int target) {
    while (*f < target) __nanosleep(64);
    __threadfence();   // acquire
}

__device__ __forceinline__ void ldsm_x4(uint32_t& r0, uint32_t& r1, uint32_t& r2, uint32_t& r3,
                                        uint32_t addr) {
    asm volatile("ldmatrix.sync.aligned.m8n8.x4.shared.b16 {%0,%1,%2,%3}, [%4];"
                 : "=r"(r0), "=r"(r1), "=r"(r2), "=r"(r3) : "r"(addr));
}

// Sense-reversing software grid barrier. Safe: all CTAs resident (occ=2 forced).
__device__ __forceinline__ void gbar(int id) {
    __syncthreads();
    if (threadIdx.x == 0) {
        volatile unsigned* genp = &g_bargen[id];
        unsigned gen = *genp;
        __threadfence();                         // release my writes
        unsigned old = atomicAdd(&g_barcnt[id], 1u);
        if (old == gridDim.x - 1u) {
            g_barcnt[id] = 0u;
            __threadfence();
            atomicAdd(&g_bargen[id], 1u);        // release all
        } else {
            while (*genp == gen) __nanosleep(32);
        }
        __threadfence();                         // acquire
    }
    __syncthreads();
}

// ============================================================================
// Phase bodies
// ============================================================================
__device__ __forceinline__ void transpose_split_tile256(const float* __restrict__ in,
                                                        __half* __restrict__ outh,
                                                        __half* __restrict__ outl,
                                                        int R, int C, int bx, int by,
                                                        float* tbuf /* 32*33 */) {
    int tx = threadIdx.x & 31, ty = threadIdx.x >> 5;   // 32 x 8
    #pragma unroll
    for (int j = 0; j < 32; j += 8)
        tbuf[(ty + j) * 33 + tx] = in[(size_t)(by + ty + j) * C + bx + tx];
    __syncthreads();
    #pragma unroll
    for (int j = 0; j < 32; j += 8) {
        float x = tbuf[tx * 33 + ty + j];
        __half h, l; split_h(x, h, l);
        size_t o = (size_t)(bx + ty + j) * R + by + tx;
        outh[o] = h; outl[o] = l;
    }
    __syncthreads();
}

__device__ __forceinline__ void f4add(float4& a, const float4 b) {
    a.x += b.x; a.y += b.y; a.z += b.z; a.w += b.w;
}

__device__ __forceinline__ void store_split4(__half* ph, __half* pl, size_t off, float4 v) {
    __half hx, hy, hz, hw, lx, ly, lz, lw;
    split_h(v.x, hx, lx); split_h(v.y, hy, ly);
    split_h(v.z, hz, lz); split_h(v.w, hw, lw);
    *(__half2*)(ph + off)     = __halves2half2(hx, hy);
    *(__half2*)(ph + off + 2) = __halves2half2(hz, hw);
    *(__half2*)(pl + off)     = __halves2half2(lx, ly);
    *(__half2*)(pl + off + 2) = __halves2half2(lz, lw);
}

// One node per warp: gather-sum + GIN combine -> split fp16; pre-init out=feat+b2.
__device__ __forceinline__ void agg_node(int node, int lane,
                                         const float* __restrict__ feat, float ep,
                                         const float* __restrict__ b2,
                                         float* __restrict__ out) {
    float4 a0 = make_float4(0.f, 0.f, 0.f, 0.f), a1 = a0, a2 = a0, a3 = a0;
    int e = g_off[node], e1 = e + g_cnt[node];
    const float4* F = (const float4*)feat;

    for (; e + 1 < e1; e += 2) {
        const float4* p0 = F + (size_t)g_csr[e]     * (D_IN / 4);
        const float4* p1 = F + (size_t)g_csr[e + 1] * (D_IN / 4);
        float4 v00 = p0[lane], v01 = p0[lane + 32], v02 = p0[lane + 64], v03 = p0[lane + 96];
        float4 v10 = p1[lane], v11 = p1[lane + 32], v12 = p1[lane + 64], v13 = p1[lane + 96];
        f4add(a0, v00); f4add(a1, v01); f4add(a2, v02); f4add(a3, v03);
        f4add(a0, v10); f4add(a1, v11); f4add(a2, v12); f4add(a3, v13);
    }
    if (e < e1) {
        const float4* p0 = F + (size_t)g_csr[e] * (D_IN / 4);
        f4add(a0, p0[lane]); f4add(a1, p0[lane + 32]);
        f4add(a2, p0[lane + 64]); f4add(a3, p0[lane + 96]);
    }

    const float4* fn = F + (size_t)node * (D_IN / 4);
    const float4* B2 = (const float4*)b2;
    float4* O = (float4*)out + (size_t)node * (D_IN / 4);
    size_t base = (size_t)node * D_IN;
    #pragma unroll
    for (int q = 0; q < 4; q++) {
        float4 f = fn[lane + 32 * q];
        float4 a = (q == 0) ? a0 : (q == 1) ? a1 : (q == 2) ? a2 : a3;
        float4 r = make_float4(fmaf(ep, f.x, a.x), fmaf(ep, f.y, a.y),
                               fmaf(ep, f.z, a.z), fmaf(ep, f.w, a.w));
        store_split4(g_Ah, g_Al, base + (lane + 32 * q) * 4, r);
        float4 bb = B2[lane + 32 * q];
        O[lane + 32 * q] = make_float4(f.x + bb.x, f.y + bb.y, f.z + bb.z, f.w + bb.w);
    }
}

// ============================================================================
// 3xFP16 GEMM tile body (R14-proven core): 128x128 out, K=512, 2-stage
// cp.async, 80B-padded rows, ldmatrix frags, term-major MMA order.
// GEMM2 epilogue: smem staging + cp.reduce.async.bulk (bulk-engine atomics)
// instead of 64 ATOMG per thread.
// ============================================================================
#define BM 128
#define BN 128
#define BK 32
#define KLOOP 512
#define HROW 40
#define HROWB 80
#define HTILE_H (BM * HROW)
#define HTILE_B (HTILE_H * 2)
#define STAGE_B (4 * HTILE_B)
#define GEMM_SMEM (2 * STAGE_B)       // 81920 (>= 64KB staging for epilogue)

__device__ __forceinline__ void cp_async16(uint32_t dst, const void* src, int src_sz) {
    asm volatile("cp.async.cg.shared.global [%0], [%1], 16, %2;"
                 :: "r"(dst), "l"(src), "r"(src_sz));
}

__device__ __forceinline__ void load_tile_p(uint32_t sbase,
                                            const __half* __restrict__ Ah, const __half* __restrict__ Al,
                                            const __half* __restrict__ Bh, const __half* __restrict__ Bl,
                                            int lda, int ldb, int m0, int n0, int k0, int tid) {
    #pragma unroll
    for (int i = 0; i < 2; i++) {
        int idx = tid + i * 256;
        int row = idx >> 2, c8 = idx & 3;
        uint32_t doff = (uint32_t)(row * HROWB + c8 * 16);
        int gm = m0 + row;
        int ok = gm < N_NODES;
        size_t aoff = (size_t)(ok ? gm : 0) * lda + k0 + c8 * 8;
        size_t boff = (size_t)(n0 + row) * ldb + k0 + c8 * 8;
        cp_async16(sbase + doff,                Ah + aoff, ok ? 16 : 0);
        cp_async16(sbase + HTILE_B + doff,      Al + aoff, ok ? 16 : 0);
        cp_async16(sbase + 2 * HTILE_B + doff,  Bh + boff, 16);
        cp_async16(sbase + 3 * HTILE_B + doff,  Bl + boff, 16);
    }
}

// NOTE: NOT volatile — pure register dataflow, lets ptxas schedule/interleave.
__device__ __forceinline__ void mma_f16(float d[4], const uint32_t a[4], const uint32_t b[2]) {
    asm("mma.sync.aligned.m16n8k16.row.col.f32.f16.f16.f32 "
        "{%0,%1,%2,%3}, {%4,%5,%6,%7}, {%8,%9}, {%0,%1,%2,%3};"
        : "+f"(d[0]), "+f"(d[1]), "+f"(d[2]), "+f"(d[3])
        : "r"(a[0]), "r"(a[1]), "r"(a[2]), "r"(a[3]), "r"(b[0]), "r"(b[1]));
}

__device__ __forceinline__ void gemm_tile_body(
    uint32_t sb, int tid,
    const __half* __restrict__ Ah, const __half* __restrict__ Al, int lda,
    const __half* __restrict__ Bh, const __half* __restrict__ Bl, int ldb,
    int m0, int n0,
    const float* __restrict__ bias,
    float* __restrict__ outp,
    __half* __restrict__ outH, __half* __restrict__ outL, int outld)
{
    const int wid = tid >> 5, lane = tid & 31;
    const int wm = wid & 1, wn = wid >> 1;       // warp tile: 64 (m) x 32 (n)
    const int lg = lane >> 2, lt = lane & 3;

    // ldmatrix per-lane address offsets
    const uint32_t aLane = (uint32_t)((lane & 15) * HROWB + (lane >> 4) * 16);
    const uint32_t bLane = (uint32_t)((((lane & 7) + ((lane >> 4) << 3)) * HROWB)
                                      + ((lane >> 3) & 1) * 16);

    float acc[4][4][4];
    #pragma unroll
    for (int i = 0; i < 4; i++)
        #pragma unroll
        for (int j = 0; j < 4; j++)
            #pragma unroll
            for (int c = 0; c < 4; c++) acc[i][j][c] = 0.f;

    const int nk = KLOOP / BK;  // 16
    load_tile_p(sb, Ah, Al, Bh, Bl, lda, ldb, m0, n0, 0, tid);
    asm volatile("cp.async.commit_group;" ::: "memory");
    load_tile_p(sb + STAGE_B, Ah, Al, Bh, Bl, lda, ldb, m0, n0, BK, tid);
    asm volatile("cp.async.commit_group;" ::: "memory");

    for (int kc = 0; kc < nk; kc++) {
        asm volatile("cp.async.wait_group 1;" ::: "memory");
        __syncthreads();
        const int buf = kc & 1;
        const uint32_t tAh = sb + buf * STAGE_B;
        const uint32_t tAl = tAh + HTILE_B;
        const uint32_t tBh = tAl + HTILE_B;
        const uint32_t tBl = tBh + HTILE_B;
        const uint32_t aBaseH = tAh + (uint32_t)(wm * 64) * HROWB + aLane;
        const uint32_t aBaseL = tAl + (uint32_t)(wm * 64) * HROWB + aLane;
        const uint32_t bBaseH = tBh + (uint32_t)(wn * 32) * HROWB + bLane;
        const uint32_t bBaseL = tBl + (uint32_t)(wn * 32) * HROWB + bLane;

        #pragma unroll
        for (int kk = 0; kk < BK; kk += 16) {
            uint32_t bh[4][2], bl[4][2];
            #pragma unroll
            for (int njp = 0; njp < 2; njp++) {
                uint32_t o = (uint32_t)(njp * 16 * HROWB + kk * 2);
                ldsm_x4(bh[2 * njp][0], bh[2 * njp][1], bh[2 * njp + 1][0], bh[2 * njp + 1][1],
                        bBaseH + o);
                ldsm_x4(bl[2 * njp][0], bl[2 * njp][1], bl[2 * njp + 1][0], bl[2 * njp + 1][1],
                        bBaseL + o);
            }
            #pragma unroll
            for (int mi = 0; mi < 4; mi++) {
                uint32_t o = (uint32_t)(mi * 16 * HROWB + kk * 2);
                uint32_t ah[4], al[4];
                ldsm_x4(ah[0], ah[1], ah[2], ah[3], aBaseH + o);
                ldsm_x4(al[0], al[1], al[2], al[3], aBaseL + o);
                // Term-major order: dependency distance on each acc = 4 MMAs.
                #pragma unroll
                for (int nj = 0; nj < 4; nj++) mma_f16(acc[mi][nj], ah, bl[nj]); // hi*lo
                #pragma unroll
                for (int nj = 0; nj < 4; nj++) mma_f16(acc[mi][nj], al, bh[nj]); // lo*hi
                #pragma unroll
                for (int nj = 0; nj < 4; nj++) mma_f16(acc[mi][nj], ah, bh[nj]); // hi*hi
            }
        }
        __syncthreads();   // all warps done reading buf before it is refilled
        if (kc + 2 < nk)
            load_tile_p(sb + (kc & 1) * STAGE_B, Ah, Al, Bh, Bl, lda, ldb,
                        m0, n0, (kc + 2) * BK, tid);
        asm volatile("cp.async.commit_group;" ::: "memory");
    }
    asm volatile("cp.async.wait_group 0;" ::: "memory");

    if (outH) {
        // ---- GEMM1 epilogue: bias + relu, split-store to Hh/Hl
        #pragma unroll
        for (int mi = 0; mi < 4; mi++) {
            #pragma unroll
            for (int half = 0; half < 2; half++) {
                int gm = m0 + wm * 64 + mi * 16 + lg + half * 8;
                if (gm >= N_NODES) continue;
                #pragma unroll
                for (int nj = 0; nj < 4; nj++) {
                    int gn = n0 + wn * 32 + nj * 8 + 2 * lt;
                    float vx = acc[mi][nj][half * 2 + 0];
                    float vy = acc[mi][nj][half * 2 + 1];
                    float2 bv = *(const float2*)(bias + gn);
                    vx = fmaxf(vx + bv.x, 0.f);
                    vy = fmaxf(vy + bv.y, 0.f);
                    __half hx, hy, lx, ly;
                    split_h(vx, hx, lx); split_h(vy, hy, ly);
                    *(__half2*)(outH + (size_t)gm * outld + gn) = __halves2half2(hx, hy);
                    *(__half2*)(outL + (size_t)gm * outld + gn) = __halves2half2(lx, ly);
                }
            }
        }
    } else {
        // ---- GEMM2 epilogue: stage fp32 tile to smem, bulk-reduce into out.
        // (last mainloop iteration ended with __syncthreads -> smem reusable)
        #pragma unroll
        for (int mi = 0; mi < 4; mi++) {
            #pragma unroll
            for (int half = 0; half < 2; half++) {
                int srow = wm * 64 + mi * 16 + lg + half * 8;
                #pragma unroll
                for (int nj = 0; nj < 4; nj++) {
                    int scol = wn * 32 + nj * 8 + 2 * lt;
                    uint32_t sa = sb + (uint32_t)(srow * BN + scol) * 4;
                    asm volatile("st.shared.v2.f32 [%0], {%1, %2};"
                                 :: "r"(sa), "f"(acc[mi][nj][half * 2 + 0]),
                                    "f"(acc[mi][nj][half * 2 + 1]));
                }
            }
        }
        asm volatile("fence.proxy.async.shared::cta;" ::: "memory");
        __syncthreads();
        if (tid < BM) {
            int gm = m0 + tid;
            if (gm < N_NODES) {
                float* gp = outp + (size_t)gm * D_IN + n0;
                uint32_t sa = sb + (uint32_t)(tid * BN) * 4;
                asm volatile(
                    "cp.reduce.async.bulk.global.shared::cta.bulk_group.add.f32 "
                    "[%0], [%1], %2;"
                    :: "l"(gp), "r"(sa), "r"(BN * 4) : "memory");
            }
        }
        asm volatile("cp.async.bulk.commit_group;" ::: "memory");
        asm volatile("cp.async.bulk.wait_group.read 0;" ::: "memory");
        __syncthreads();   // nobody reuses smem until bulk reads are done
    }
}

// ============================================================================
// THE single persistent kernel: CSR build + transposes + agg + GEMM1 + GEMM2
// ============================================================================
__global__ __launch_bounds__(256, 2) void mono_kernel(
    const float* __restrict__ feat,
    const float* __restrict__ W1, const float* __restrict__ b1,
    const float* __restrict__ W2, const float* __restrict__ b2,
    const float* __restrict__ eps,
    const int* __restrict__ src, const int* __restrict__ dst,
    float* __restrict__ out)
{
    extern __shared__ char smem[];
    __shared__ int s_t;
    __shared__ int s_ws[8];
    __shared__ int s_blkbase;
    uint32_t sb = smem_to_u32(smem);
    const int tid = threadIdx.x, wid = tid >> 5, lane = tid & 31;
    const int cta = blockIdx.x, nctas = gridDim.x;

    // ---- Phase A: zero counts + flags + queue
    for (int i = cta * 256 + tid; i < N_NODES; i += nctas * 256) g_cnt[i] = 0;
    if (cta == 0) {
        if (tid < NMB) { g_adone[tid] = 0; g_hdone[tid] = 0; }
        if (tid == 200) { g_base_ctr = 0; g_qhead = 0; }
    }
    gbar(0);

    // ---- Phase B: edge histogram + weight transposes (independent, overlap)
    {
        int echunk = (N_EDGES + nctas - 1) / nctas;
        int e0 = cta * echunk, e1 = min(e0 + echunk, N_EDGES);
        for (int i = e0 + tid; i < e1; i += 256) atomicAdd(&g_cnt[dst[i]], 1);

        int tchunk = (1024 + nctas - 1) / nctas;   // 1024 transpose tiles
        int t0 = cta * tchunk, t1 = min(t0 + tchunk, 1024);
        for (int tt = t0; tt < t1; tt++) {
            __syncthreads();
            if (tt < 512) {
                int bx = (tt & 31) * 32, by = (tt >> 5) * 32;  // W1 [512,1024]
                transpose_split_tile256(W1, g_W1h, g_W1l, D_IN, D_HID, bx, by, (float*)smem);
            } else {
                int idx = tt - 512;
                int bx = (idx & 15) * 32, by = (idx >> 4) * 32; // W2 [1024,512]
                transpose_split_tile256(W2, g_W2h, g_W2l, D_HID, D_IN, bx, by, (float*)smem);
            }
        }
    }
    gbar(1);

    // ---- Phase C: block scan + atomic base (first 40 CTAs)
    if (cta < (N_NODES + 255) / 256) {
        int i = cta * 256 + tid;
        int v = (i < N_NODES) ? g_cnt[i] : 0;
        int x = v;
        #pragma unroll
        for (int o = 1; o < 32; o <<= 1) {
            int y = __shfl_up_sync(0xFFFFFFFFu, x, o);
            if ((tid & 31) >= o) x += y;
        }
        if ((tid & 31) == 31) s_ws[wid] = x;
        __syncthreads();
        if (tid == 0) {
            int s = 0;
            #pragma unroll
            for (int j = 0; j < 8; j++) { int tmp = s_ws[j]; s_ws[j] = s; s += tmp; }
            s_blkbase = atomicAdd(&g_base_ctr, s);
        }
        __syncthreads();
        int ex = s_blkbase + s_ws[wid] + x - v;
        if (i < N_NODES) { g_off[i] = ex; g_cur[i] = ex; }
    }
    gbar(2);

    // ---- Phase D: CSR scatter
    {
        int echunk = (N_EDGES + nctas - 1) / nctas;
        int e0 = cta * echunk, e1 = min(e0 + echunk, N_EDGES);
        for (int i = e0 + tid; i < e1; i += 256) {
            int d = dst[i];
            int p = atomicAdd(&g_cur[d], 1);
            g_csr[p] = src[i];
        }
    }
    gbar(3);

    // ---- Phase E: tile queue (agg -> GEMM1 -> GEMM2), R14 ordering
    const float ep = 1.0f + eps[0];
    for (;;) {
        __syncthreads();
        if (tid == 0) s_t = atomicAdd(&g_qhead, 1);
        __syncthreads();
        int t = s_t;
        if (t >= TILE_TOTAL) return;

        if (t < TILE_AGG_END) {
            int base = t * 32;
            #pragma unroll
            for (int i = 0; i < 4; i++) {
                int node = base + wid * 4 + i;
                if (node < N_NODES) agg_node(node, lane, feat, ep, b2, out);
            }
            __threadfence();
            __syncthreads();
            if (tid == 0) atomicAdd(&g_adone[t >> 2], 1);
        } else if (t < TILE_G1_END) {
            int u = t - TILE_AGG_END;
            int m = u >> 3, n = u & 7;
            wait_flag(&g_adone[m], 4);
            gemm_tile_body(sb, tid,
                           g_Ah, g_Al, D_IN, g_W1h, g_W1l, D_IN,
                           m * 128, n * 128, b1, nullptr, g_Hh, g_Hl, D_HID);
            __threadfence();
            __syncthreads();
            if (tid == 0) atomicAdd(&g_hdone[m], 1);
        } else {
            int u = t - TILE_G1_END;
            int m = u >> 3, r = u & 7, n2 = r >> 1, kc = r & 1;
            wait_flag(&g_hdone[m], 8);
            gemm_tile_body(sb, tid,
                           g_Hh + kc * 512, g_Hl + kc * 512, D_HID,
                           g_W2h + kc * 512, g_W2l + kc * 512, D_HID,
                           m * 128, n2 * 128, nullptr, out, nullptr, nullptr, 0);
        }
    }
}

// ============================================================================
// kernel_launch — ONE launch
// ============================================================================
extern "C" void kernel_launch(void* const* d_in, const int* in_sizes, int n_in,
                              void* d_out, int out_size) {
    const float* feat = (const float*)d_in[0];
    const float* W1   = (const float*)d_in[1];
    const float* b1   = (const float*)d_in[2];
    const float* W2   = (const float*)d_in[3];
    const float* b2   = (const float*)d_in[4];
    const float* eps  = (const float*)d_in[5];
    const int*   src  = (const int*)d_in[6];
    const int*   dst  = (const int*)d_in[7];
    float* out = (float*)d_out;

    static int grid = 0;
    if (grid == 0) {
        int nsm = 148;
        cudaDeviceGetAttribute(&nsm, cudaDevAttrMultiProcessorCount, 0);
        grid = 2 * nsm;   // matches __launch_bounds__(256, 2): all CTAs resident
    }

    cudaFuncSetAttribute(mono_kernel,
                         cudaFuncAttributeMaxDynamicSharedMemorySize, GEMM_SMEM);

    mono_kernel<<<grid, 256, GEMM_SMEM>>>(feat, W1, b1, W2, b2, eps, src, dst, out);
}